// round 2
// baseline (speedup 1.0000x reference)
#include <cuda_runtime.h>
#include <cstdint>

#define BB 16
#define CC 80
#define TX 512
#define TY 2048
#define NEGF (-1000000000.0f)

// Output layout (flat concat, fp32):
// z_T [B,TY,C], y_mean_T [B,TY,C], y_ls_T [B,TY,C], attn_T [B,TY,TX], dur [B,TX,1]
#define N_ZT   ((size_t)BB * TY * CC)
#define OFF_Z   ((size_t)0)
#define OFF_M   (N_ZT)
#define OFF_L   (2 * N_ZT)
#define OFF_AT  (3 * N_ZT)
#define OFF_DUR (3 * N_ZT + (size_t)BB * TY * TX)

// ---------------- scratch ----------------
__device__ float g_a   [BB * CC * TX];
__device__ float g_ms  [BB * CC * TX];
__device__ float g_bias[BB * TX];
__device__ float g_logp[(size_t)BB * TY * TX];
__device__ int   g_xs  [BB * TY];
__device__ float g_omT [BB * TX * CC];   // [b][x][c]
__device__ float g_olsT[BB * TX * CC];

// ---------------- f32x2 helpers ----------------
__device__ __forceinline__ unsigned long long pack2(float lo, float hi) {
    unsigned long long r;
    asm("mov.b64 %0, {%1, %2};" : "=l"(r) : "f"(lo), "f"(hi));
    return r;
}
__device__ __forceinline__ float2 unpack2(unsigned long long v) {
    float lo, hi;
    asm("mov.b64 {%0, %1}, %2;" : "=f"(lo), "=f"(hi) : "l"(v));
    return make_float2(lo, hi);
}
__device__ __forceinline__ unsigned long long fma2(unsigned long long a,
                                                   unsigned long long b,
                                                   unsigned long long c) {
    unsigned long long d;
    asm("fma.rn.f32x2 %0, %1, %2, %3;" : "=l"(d) : "l"(a), "l"(b), "l"(c));
    return d;
}

// ---------------- kernel 1: prep ----------------
__global__ void __launch_bounds__(128) prep_kernel(const float* __restrict__ om,
                                                   const float* __restrict__ ols) {
    int b = blockIdx.y;
    int x = blockIdx.x * 128 + threadIdx.x;
    float acc = 0.0f;
    for (int c = 0; c < CC; ++c) {
        size_t i = ((size_t)b * CC + c) * TX + x;
        float ls = ols[i];
        float m  = om[i];
        float a  = expf(-2.0f * ls);
        g_a[i]  = a;
        g_ms[i] = m * a;
        acc += -0.9189385332046727f - ls - 0.5f * m * m * a;
    }
    g_bias[b * TX + x] = acc;
}

// ---------------- kernel 2: logp GEMM (f32x2, 128x64 tile, 8x8/thread) ----------------
#define GBX 128
#define GBY 64
#define GKC 16
__global__ void __launch_bounds__(128, 2) gemm_logp(const float* __restrict__ z,
                                                    const int* __restrict__ xlen,
                                                    const int* __restrict__ ylen) {
    __shared__ __align__(16) float As[GKC][GBX];
    __shared__ __align__(16) float Ms[GKC][GBX];
    __shared__ __align__(16) float Z1s[GKC][GBY];
    __shared__ __align__(16) float Z2s[GKC][GBY];

    int b  = blockIdx.z;
    int x0 = blockIdx.x * GBX;
    int y0 = blockIdx.y * GBY;
    int tid = threadIdx.x;
    int txi = tid & 15;       // 16 x-groups of 8
    int tyi = tid >> 4;       // 8 y-groups of 8
    int xl = txi * 8;
    int yl = tyi * 8;

    unsigned long long acc[8][4];   // [y][xpair]
#pragma unroll
    for (int i = 0; i < 8; ++i)
#pragma unroll
        for (int j = 0; j < 4; ++j) acc[i][j] = 0ULL;

    for (int kc = 0; kc < CC; kc += GKC) {
        __syncthreads();
        // A/M: 16x128 floats = 512 float4, 4 per thread
#pragma unroll
        for (int i = 0; i < 4; ++i) {
            int f  = tid + i * 128;
            int r  = f >> 5;
            int c4 = (f & 31) << 2;
            size_t gi = ((size_t)b * CC + kc + r) * TX + x0 + c4;
            *(float4*)&As[r][c4] = *(const float4*)&g_a[gi];
            *(float4*)&Ms[r][c4] = *(const float4*)&g_ms[gi];
        }
        // Z: 16x64 floats = 256 float4, 2 per thread
#pragma unroll
        for (int i = 0; i < 2; ++i) {
            int f  = tid + i * 128;
            int r  = f >> 4;
            int c4 = (f & 15) << 2;
            size_t gi = ((size_t)b * CC + kc + r) * TY + y0 + c4;
            float4 zv = *(const float4*)&z[gi];
            *(float4*)&Z1s[r][c4] = zv;
            float4 q = make_float4(-0.5f * zv.x * zv.x, -0.5f * zv.y * zv.y,
                                   -0.5f * zv.z * zv.z, -0.5f * zv.w * zv.w);
            *(float4*)&Z2s[r][c4] = q;
        }
        __syncthreads();
#pragma unroll
        for (int k = 0; k < GKC; ++k) {
            ulonglong2 A0 = *(const ulonglong2*)&As[k][xl];
            ulonglong2 A1 = *(const ulonglong2*)&As[k][xl + 4];
            ulonglong2 M0 = *(const ulonglong2*)&Ms[k][xl];
            ulonglong2 M1 = *(const ulonglong2*)&Ms[k][xl + 4];
            float4 z1a = *(const float4*)&Z1s[k][yl];
            float4 z1b = *(const float4*)&Z1s[k][yl + 4];
            float4 z2a = *(const float4*)&Z2s[k][yl];
            float4 z2b = *(const float4*)&Z2s[k][yl + 4];
            unsigned long long aa[4] = {A0.x, A0.y, A1.x, A1.y};
            unsigned long long mm[4] = {M0.x, M0.y, M1.x, M1.y};
            float z1v[8] = {z1a.x, z1a.y, z1a.z, z1a.w, z1b.x, z1b.y, z1b.z, z1b.w};
            float z2v[8] = {z2a.x, z2a.y, z2a.z, z2a.w, z2b.x, z2b.y, z2b.z, z2b.w};
#pragma unroll
            for (int yy = 0; yy < 8; ++yy) {
                unsigned long long d2 = pack2(z2v[yy], z2v[yy]);
                unsigned long long d1 = pack2(z1v[yy], z1v[yy]);
#pragma unroll
                for (int xp = 0; xp < 4; ++xp) {
                    acc[yy][xp] = fma2(aa[xp], d2, acc[yy][xp]);
                    acc[yy][xp] = fma2(mm[xp], d1, acc[yy][xp]);
                }
            }
        }
    }

    int txL = xlen[b], tyL = ylen[b];
    float bv[8];
    *(float4*)&bv[0] = *(const float4*)&g_bias[b * TX + x0 + xl];
    *(float4*)&bv[4] = *(const float4*)&g_bias[b * TX + x0 + xl + 4];
#pragma unroll
    for (int yy = 0; yy < 8; ++yy) {
        int y = y0 + yl + yy;
        bool yok = (y < tyL);
        float row[8];
#pragma unroll
        for (int xp = 0; xp < 4; ++xp) {
            float2 u = unpack2(acc[yy][xp]);
            row[2 * xp]     = u.x;
            row[2 * xp + 1] = u.y;
        }
        float o[8];
#pragma unroll
        for (int j = 0; j < 8; ++j) {
            int x = x0 + xl + j;
            o[j] = (yok && x < txL) ? (bv[j] + row[j]) : 0.0f;
        }
        size_t base = ((size_t)b * TY + y) * TX + x0 + xl;
        *(float4*)&g_logp[base]     = make_float4(o[0], o[1], o[2], o[3]);
        *(float4*)&g_logp[base + 4] = make_float4(o[4], o[5], o[6], o[7]);
    }
}

// ---------------- kernel 3: fused DP + transposes + attn zero-fill ----------------
// blocks 0..15: per-batch DP (1 warp), smem: sd16[TY*32] u16 (128KB) + dur[512] int
// blocks 16..271: z transpose (b, 128-s tile) -> out z_T
// blocks 272..335: om transpose -> g_omT
// blocks 336..399: ols transpose -> g_olsT
// blocks 400..511: zero-fill attn region
#define FWD_SMEM (TY * 32 * 2 + TX * 4)
#define NFILL 112

__device__ __forceinline__ void dp_column(float (&r)[16], const float cc[16],
                                          unsigned short* sd16, int y, int lane) {
    float left = __shfl_up_sync(0xffffffffu, r[15], 1);
    if (lane == 0) left = NEGF;
    unsigned bits = 0;
#pragma unroll
    for (int i = 15; i >= 1; --i) {
        float vd = r[i - 1];
        if (vd > r[i]) bits |= (1u << i);
        r[i] = cc[i] + fmaxf(r[i], vd);
    }
    if (left > r[0]) bits |= 1u;
    r[0] = cc[0] + fmaxf(r[0], left);
    sd16[(y - 1) * 32 + lane] = (unsigned short)bits;
}

__global__ void __launch_bounds__(512) fwd_fused(const float* __restrict__ z,
                                                 const float* __restrict__ om,
                                                 const float* __restrict__ ols,
                                                 const int* __restrict__ xlen,
                                                 const int* __restrict__ ylen,
                                                 float* __restrict__ out) {
    extern __shared__ unsigned char smem_raw[];
    int bid = blockIdx.x;
    int tid = threadIdx.x;

    if (bid < 16) {
        // ---- DP: 1 warp per batch ----
        if (tid >= 32) return;
        int lane = tid;
        int b = bid;
        unsigned short* sd16 = (unsigned short*)smem_raw;
        int* sdur = (int*)(smem_raw + (size_t)TY * 32 * 2);
#pragma unroll
        for (int i = 0; i < 16; ++i) sdur[i * 32 + lane] = 0;

        const float* lp = &g_logp[(size_t)b * TY * TX];
        size_t lbase = (size_t)lane * 16;

        float r[16];
        float4 buf[4][4];
#pragma unroll
        for (int p = 0; p < 4; ++p)
#pragma unroll
            for (int q = 0; q < 4; ++q)
                buf[p][q] = *(const float4*)&lp[(size_t)p * TX + lbase + q * 4];

        // y = 0
        {
            float cc[16];
            *(float4*)&cc[0]  = buf[0][0];
            *(float4*)&cc[4]  = buf[0][1];
            *(float4*)&cc[8]  = buf[0][2];
            *(float4*)&cc[12] = buf[0][3];
#pragma unroll
            for (int q = 0; q < 4; ++q)
                buf[0][q] = *(const float4*)&lp[(size_t)4 * TX + lbase + q * 4];
#pragma unroll
            for (int i = 0; i < 16; ++i)
                r[i] = (lane == 0 && i == 0) ? cc[0] : NEGF;
        }
        // y = 1..3
#pragma unroll
        for (int j = 1; j < 4; ++j) {
            float cc[16];
            *(float4*)&cc[0]  = buf[j][0];
            *(float4*)&cc[4]  = buf[j][1];
            *(float4*)&cc[8]  = buf[j][2];
            *(float4*)&cc[12] = buf[j][3];
#pragma unroll
            for (int q = 0; q < 4; ++q)
                buf[j][q] = *(const float4*)&lp[(size_t)(j + 4) * TX + lbase + q * 4];
            dp_column(r, cc, sd16, j, lane);
        }
        // y = 4..TY-1
        for (int g = 4; g < TY; g += 4) {
#pragma unroll
            for (int j = 0; j < 4; ++j) {
                int y = g + j;
                float cc[16];
                *(float4*)&cc[0]  = buf[j][0];
                *(float4*)&cc[4]  = buf[j][1];
                *(float4*)&cc[8]  = buf[j][2];
                *(float4*)&cc[12] = buf[j][3];
                if (y + 4 < TY) {
#pragma unroll
                    for (int q = 0; q < 4; ++q)
                        buf[j][q] = *(const float4*)&lp[(size_t)(y + 4) * TX + lbase + q * 4];
                }
                dp_column(r, cc, sd16, y, lane);
            }
        }
        __syncwarp();

        int txL = xlen[b], tyL = ylen[b];
        if (lane == 0) {
            int idx = txL - 1;
            for (int y = TY - 1; y >= 0; --y) {
                if (y >= tyL) { g_xs[b * TY + y] = -1; continue; }
                g_xs[b * TY + y] = idx;
                sdur[idx]++;
                int mv = 0;
                if (idx > 0) {
                    if (idx == y) {
                        mv = 1;
                    } else {
                        unsigned w = sd16[(y - 1) * 32 + (idx >> 4)];
                        mv = (w >> (idx & 15)) & 1;
                    }
                }
                idx -= mv;
            }
        }
        __syncwarp();
#pragma unroll
        for (int i = 0; i < 16; ++i) {
            int x = i * 32 + lane;
            float dv = log1pf((float)sdur[x]);
            out[OFF_DUR + b * TX + x] = (x < txL) ? dv : 0.0f;
        }
    } else if (bid < 400) {
        // ---- transposes: [C][N]-major -> [N][C]-major, tiles of 128 n ----
        float* tile = (float*)smem_raw;   // [80][129]
        int role, idx;
        const float* src;
        int srcN;
        if (bid < 272)      { role = 0; idx = bid - 16;  src = z;   srcN = TY; }
        else if (bid < 336) { role = 1; idx = bid - 272; src = om;  srcN = TX; }
        else                { role = 2; idx = bid - 336; src = ols; srcN = TX; }
        int tilesPerB = (role == 0) ? 16 : 4;
        int b  = idx / tilesPerB;
        int n0 = (idx % tilesPerB) * 128;
        int tyL = ylen[b];
        // load: 80 rows x 128 = 2560 float4
#pragma unroll
        for (int i = 0; i < 5; ++i) {
            int f  = tid + i * 512;
            int c  = f >> 5;
            int s4 = (f & 31) << 2;
            float4 v = *(const float4*)&src[((size_t)b * CC + c) * srcN + n0 + s4];
            int base = c * 129 + s4;
            tile[base]     = v.x;
            tile[base + 1] = v.y;
            tile[base + 2] = v.z;
            tile[base + 3] = v.w;
        }
        __syncthreads();
        // store: 128 n x 80 c = 2560 float4 (c-fastest)
#pragma unroll
        for (int i = 0; i < 5; ++i) {
            int f  = tid + i * 512;
            int sl = f / 20;
            int c4 = (f % 20) * 4;
            float4 o;
            o.x = tile[(c4 + 0) * 129 + sl];
            o.y = tile[(c4 + 1) * 129 + sl];
            o.z = tile[(c4 + 2) * 129 + sl];
            o.w = tile[(c4 + 3) * 129 + sl];
            int n = n0 + sl;
            if (role == 0) {
                if (n >= tyL) o = make_float4(0.f, 0.f, 0.f, 0.f);
                *(float4*)&out[OFF_Z + ((size_t)b * TY + n) * CC + c4] = o;
            } else {
                float* dst = (role == 1) ? g_omT : g_olsT;
                *(float4*)&dst[((size_t)b * TX + n) * CC + c4] = o;
            }
        }
    } else {
        // ---- zero-fill attn region: 16M float4 ----
        size_t total = (size_t)BB * TY * TX / 4;
        float4* p = (float4*)&out[OFF_AT];
        float4 zv = make_float4(0.f, 0.f, 0.f, 0.f);
        size_t start = (size_t)(bid - 400) * 512 + tid;
        for (size_t i = start; i < total; i += (size_t)NFILL * 512)
            p[i] = zv;
    }
}

// ---------------- kernel 4: gathers + attn ones ----------------
__global__ void __launch_bounds__(256) gather_kernel(float* __restrict__ out) {
    int t = blockIdx.x * 256 + threadIdx.x;
    if (t >= BB * TY * 20) return;
    int bs = t / 20;
    int c4 = (t % 20) * 4;
    int b  = bs >> 11;
    int xs = g_xs[bs];
    float4 m = make_float4(0.f, 0.f, 0.f, 0.f), l = m;
    if (xs >= 0) {
        size_t rb = ((size_t)b * TX + xs) * CC + c4;
        m = *(const float4*)&g_omT[rb];
        l = *(const float4*)&g_olsT[rb];
        if (c4 == 0) out[OFF_AT + (size_t)bs * TX + xs] = 1.0f;
    }
    *(float4*)&out[OFF_M + (size_t)bs * CC + c4] = m;
    *(float4*)&out[OFF_L + (size_t)bs * CC + c4] = l;
}

// ---------------- launch ----------------
extern "C" void kernel_launch(void* const* d_in, const int* in_sizes, int n_in,
                              void* d_out, int out_size) {
    const float* om   = (const float*)d_in[0];
    const float* ols  = (const float*)d_in[1];
    const float* z    = (const float*)d_in[2];
    const int*   xlen = (const int*)d_in[3];
    const int*   ylen = (const int*)d_in[4];
    float* out = (float*)d_out;

    cudaFuncSetAttribute(fwd_fused, cudaFuncAttributeMaxDynamicSharedMemorySize, FWD_SMEM);

    prep_kernel<<<dim3(TX / 128, BB), 128>>>(om, ols);
    gemm_logp<<<dim3(TX / GBX, TY / GBY, BB), 128>>>(z, xlen, ylen);
    fwd_fused<<<512, 512, FWD_SMEM>>>(z, om, ols, xlen, ylen, out);
    gather_kernel<<<(BB * TY * 20 + 255) / 256, 256>>>(out);
}

// round 4
// speedup vs baseline: 1.3633x; 1.3633x over previous
#include <cuda_runtime.h>
#include <cstdint>

#define BB 16
#define CC 80
#define TX 512
#define TY 2048
#define NEGF (-1000000000.0f)

// Output layout (flat concat, fp32):
// z_T [B,TY,C], y_mean_T [B,TY,C], y_ls_T [B,TY,C], attn_T [B,TY,TX], dur [B,TX,1]
#define N_ZT   ((size_t)BB * TY * CC)
#define OFF_Z   ((size_t)0)
#define OFF_M   (N_ZT)
#define OFF_L   (2 * N_ZT)
#define OFF_AT  (3 * N_ZT)
#define OFF_DUR (3 * N_ZT + (size_t)BB * TY * TX)

// ---------------- scratch ----------------
__device__ float g_a   [BB * CC * TX];
__device__ float g_ms  [BB * CC * TX];
__device__ float g_bias[BB * TX];
__device__ float g_logp[(size_t)BB * TY * TX];
__device__ int   g_xs  [BB * TY];
__device__ float g_omT [BB * TX * CC];   // [b][x][c]
__device__ float g_olsT[BB * TX * CC];

// ---------------- f32x2 helpers ----------------
__device__ __forceinline__ unsigned long long pack2(float lo, float hi) {
    unsigned long long r;
    asm("mov.b64 %0, {%1, %2};" : "=l"(r) : "f"(lo), "f"(hi));
    return r;
}
__device__ __forceinline__ float2 unpack2(unsigned long long v) {
    float lo, hi;
    asm("mov.b64 {%0, %1}, %2;" : "=f"(lo), "=f"(hi) : "l"(v));
    return make_float2(lo, hi);
}
__device__ __forceinline__ unsigned long long fma2(unsigned long long a,
                                                   unsigned long long b,
                                                   unsigned long long c) {
    unsigned long long d;
    asm("fma.rn.f32x2 %0, %1, %2, %3;" : "=l"(d) : "l"(a), "l"(b), "l"(c));
    return d;
}
__device__ __forceinline__ unsigned swz(unsigned b) {
    return b ^ ((b >> 3) & 0x70u);
}

// ---------------- kernel 1: prep ----------------
__global__ void __launch_bounds__(128) prep_kernel(const float* __restrict__ om,
                                                   const float* __restrict__ ols) {
    int b = blockIdx.y;
    int x = blockIdx.x * 128 + threadIdx.x;
    float acc = 0.0f;
    for (int c = 0; c < CC; ++c) {
        size_t i = ((size_t)b * CC + c) * TX + x;
        float ls = ols[i];
        float m  = om[i];
        float a  = expf(-2.0f * ls);
        g_a[i]  = a;
        g_ms[i] = m * a;
        acc += -0.9189385332046727f - ls - 0.5f * m * m * a;
    }
    g_bias[b * TX + x] = acc;
}

// ---------------- kernel 2: pre_out (transposes + attn zero-fill) ----------------
#define NFILL 112
__global__ void __launch_bounds__(512) pre_out(const float* __restrict__ z,
                                               const float* __restrict__ om,
                                               const float* __restrict__ ols,
                                               const int* __restrict__ ylen,
                                               float* __restrict__ out) {
    __shared__ float tile[CC * 129];
    int bid = blockIdx.x;
    int tid = threadIdx.x;
    if (bid < 384) {
        int role, idx;
        const float* src;
        int srcN;
        if (bid < 256)      { role = 0; idx = bid;       src = z;   srcN = TY; }
        else if (bid < 320) { role = 1; idx = bid - 256; src = om;  srcN = TX; }
        else                { role = 2; idx = bid - 320; src = ols; srcN = TX; }
        int tilesPerB = (role == 0) ? 16 : 4;
        int b  = idx / tilesPerB;
        int n0 = (idx % tilesPerB) * 128;
        int tyL = ylen[b];
#pragma unroll
        for (int i = 0; i < 5; ++i) {
            int f  = tid + i * 512;
            int c  = f >> 5;
            int s4 = (f & 31) << 2;
            float4 v = *(const float4*)&src[((size_t)b * CC + c) * srcN + n0 + s4];
            int base = c * 129 + s4;
            tile[base]     = v.x;
            tile[base + 1] = v.y;
            tile[base + 2] = v.z;
            tile[base + 3] = v.w;
        }
        __syncthreads();
#pragma unroll
        for (int i = 0; i < 5; ++i) {
            int f  = tid + i * 512;
            int sl = f / 20;
            int c4 = (f % 20) * 4;
            float4 o;
            o.x = tile[(c4 + 0) * 129 + sl];
            o.y = tile[(c4 + 1) * 129 + sl];
            o.z = tile[(c4 + 2) * 129 + sl];
            o.w = tile[(c4 + 3) * 129 + sl];
            int n = n0 + sl;
            if (role == 0) {
                if (n >= tyL) o = make_float4(0.f, 0.f, 0.f, 0.f);
                *(float4*)&out[OFF_Z + ((size_t)b * TY + n) * CC + c4] = o;
            } else {
                float* dst = (role == 1) ? g_omT : g_olsT;
                *(float4*)&dst[((size_t)b * TX + n) * CC + c4] = o;
            }
        }
    } else {
        size_t total = (size_t)BB * TY * TX / 4;
        float4* p = (float4*)&out[OFF_AT];
        float4 zv = make_float4(0.f, 0.f, 0.f, 0.f);
        size_t start = (size_t)(bid - 384) * 512 + tid;
        for (size_t i = start; i < total; i += (size_t)NFILL * 512)
            p[i] = zv;
    }
}

// ---------------- kernel 3: logp GEMM (f32x2, dup-A smem, 128x128 tile) ----------------
#define GEMM_SMEM 49152
__global__ void __launch_bounds__(256, 2) gemm_logp(const float* __restrict__ z,
                                                    const int* __restrict__ xlen,
                                                    const int* __restrict__ ylen) {
    extern __shared__ __align__(16) unsigned char gsm[];
    unsigned char* smA  = gsm;
    unsigned char* smM  = gsm + 16384;
    unsigned char* smZ1 = gsm + 32768;
    unsigned char* smZ2 = gsm + 40960;

    int b  = blockIdx.z;
    int x0 = blockIdx.x * 128;
    int y0 = blockIdx.y * 128;
    int tid = threadIdx.x;
    int txi = tid & 15;
    int tyi = tid >> 4;
    int xl = txi * 8;
    int yl = tyi * 8;

    unsigned aoff[4];
#pragma unroll
    for (int g = 0; g < 4; ++g) aoff[g] = swz((unsigned)(txi * 64 + g * 16));
    unsigned zoff = (unsigned)(tyi * 32);

    unsigned long long acc[8][4];   // [x_local][y_pair]
#pragma unroll
    for (int i = 0; i < 8; ++i)
#pragma unroll
        for (int j = 0; j < 4; ++j) acc[i][j] = 0ULL;

    for (int kc = 0; kc < CC; kc += 16) {
        __syncthreads();
        // A/M: 16 rows x 128 x ; 2 float4 per thread, store duplicated+swizzled
#pragma unroll
        for (int i = 0; i < 2; ++i) {
            int f  = tid + i * 256;
            int r  = f >> 5;
            int c4 = (f & 31) << 2;
            size_t gi = ((size_t)b * CC + kc + r) * TX + x0 + c4;
            float4 av = *(const float4*)&g_a[gi];
            float4 mv = *(const float4*)&g_ms[gi];
            // FIX: each 16B chunk gets its own swizzled address (swz(base)+16 != swz(base+16))
            unsigned sb0 = swz((unsigned)(c4 * 8));
            unsigned sb1 = swz((unsigned)(c4 * 8 + 16));
            *(ulonglong2*)(smA + r * 1024 + sb0) = make_ulonglong2(pack2(av.x, av.x), pack2(av.y, av.y));
            *(ulonglong2*)(smA + r * 1024 + sb1) = make_ulonglong2(pack2(av.z, av.z), pack2(av.w, av.w));
            *(ulonglong2*)(smM + r * 1024 + sb0) = make_ulonglong2(pack2(mv.x, mv.x), pack2(mv.y, mv.y));
            *(ulonglong2*)(smM + r * 1024 + sb1) = make_ulonglong2(pack2(mv.z, mv.z), pack2(mv.w, mv.w));
        }
        // Z: 16 rows x 128 y ; 2 float4 per thread, store as y-pairs
#pragma unroll
        for (int i = 0; i < 2; ++i) {
            int f  = tid + i * 256;
            int r  = f >> 5;
            int c4 = (f & 31) << 2;
            size_t gi = ((size_t)b * CC + kc + r) * TY + y0 + c4;
            float4 zv = *(const float4*)&z[gi];
            ulonglong2* p1 = (ulonglong2*)(smZ1 + r * 512 + (f & 31) * 16);
            ulonglong2* p2 = (ulonglong2*)(smZ2 + r * 512 + (f & 31) * 16);
            *p1 = make_ulonglong2(pack2(zv.x, zv.y), pack2(zv.z, zv.w));
            *p2 = make_ulonglong2(pack2(-0.5f * zv.x * zv.x, -0.5f * zv.y * zv.y),
                                  pack2(-0.5f * zv.z * zv.z, -0.5f * zv.w * zv.w));
        }
        __syncthreads();
#pragma unroll
        for (int k = 0; k < 16; ++k) {
            const unsigned char* rowA = smA + k * 1024;
            const unsigned char* rowM = smM + k * 1024;
            ulonglong2 z1a = *(const ulonglong2*)(smZ1 + k * 512 + zoff);
            ulonglong2 z1b = *(const ulonglong2*)(smZ1 + k * 512 + zoff + 16);
            ulonglong2 z2a = *(const ulonglong2*)(smZ2 + k * 512 + zoff);
            ulonglong2 z2b = *(const ulonglong2*)(smZ2 + k * 512 + zoff + 16);
            unsigned long long z1p[4] = {z1a.x, z1a.y, z1b.x, z1b.y};
            unsigned long long z2p[4] = {z2a.x, z2a.y, z2b.x, z2b.y};
#pragma unroll
            for (int g = 0; g < 4; ++g) {
                ulonglong2 a2 = *(const ulonglong2*)(rowA + aoff[g]);
                ulonglong2 m2 = *(const ulonglong2*)(rowM + aoff[g]);
#pragma unroll
                for (int yp = 0; yp < 4; ++yp) {
                    acc[2 * g][yp]     = fma2(a2.x, z2p[yp], acc[2 * g][yp]);
                    acc[2 * g][yp]     = fma2(m2.x, z1p[yp], acc[2 * g][yp]);
                    acc[2 * g + 1][yp] = fma2(a2.y, z2p[yp], acc[2 * g + 1][yp]);
                    acc[2 * g + 1][yp] = fma2(m2.y, z1p[yp], acc[2 * g + 1][yp]);
                }
            }
        }
    }

    // epilogue
    int txL = xlen[b], tyL = ylen[b];
    float bv[8];
    *(float4*)&bv[0] = *(const float4*)&g_bias[b * TX + x0 + xl];
    *(float4*)&bv[4] = *(const float4*)&g_bias[b * TX + x0 + xl + 4];
#pragma unroll
    for (int yy = 0; yy < 8; ++yy) {
        int y = y0 + yl + yy;
        bool yok = (y < tyL);
        int yp = yy >> 1;
        bool hi = (yy & 1);
        float o[8];
#pragma unroll
        for (int j = 0; j < 8; ++j) {
            float2 u = unpack2(acc[j][yp]);
            float v = hi ? u.y : u.x;
            int x = x0 + xl + j;
            o[j] = (yok && x < txL) ? (bv[j] + v) : 0.0f;
        }
        size_t base = ((size_t)b * TY + y) * TX + x0 + xl;
        *(float4*)&g_logp[base]     = make_float4(o[0], o[1], o[2], o[3]);
        *(float4*)&g_logp[base + 4] = make_float4(o[4], o[5], o[6], o[7]);
    }
}

// ---------------- kernel 4: DP forward + backtrack (256 thr, reg-resident V) ----------------
#define FWD_SMEM (TY * 16 * 4 + TY * 4 + 64)
__global__ void __launch_bounds__(256) fwd_kernel(const int* __restrict__ xlen,
                                                  const int* __restrict__ ylen,
                                                  float* __restrict__ out) {
    extern __shared__ unsigned char fsm[];
    unsigned* sd = (unsigned*)fsm;
    int* sxs = (int*)(fsm + TY * 16 * 4);
    float* bnd = (float*)(fsm + TY * 16 * 4 + TY * 4);

    int b = blockIdx.x;
    int tid = threadIdx.x;
    int warp = tid >> 5, lane = tid & 31;
    const float* lp = &g_logp[(size_t)b * TY * TX];
    const float2* lp2 = (const float2*)lp;

    float2 pf[4];
#pragma unroll
    for (int q = 0; q < 4; ++q) pf[q] = lp2[q * 256 + tid];

    float r0, r1, bl;
    // y = 0
    {
        float2 cc = pf[0];
        r0 = (tid == 0) ? cc.x : NEGF;
        r1 = NEGF;
        pf[0] = lp2[4 * 256 + tid];
        if (lane == 31) bnd[0 * 8 + warp] = r1;
        __syncthreads();
        bl = (warp > 0) ? bnd[0 * 8 + warp - 1] : NEGF;
    }
    // y = 1..3
#pragma unroll
    for (int j = 1; j < 4; ++j) {
        int y = j;
        float2 cc = pf[j];
        pf[j] = lp2[(j + 4) * 256 + tid];
        float vd0 = __shfl_up_sync(0xffffffffu, r1, 1);
        if (lane == 0) vd0 = bl;
        unsigned be = __ballot_sync(0xffffffffu, vd0 > r0);
        unsigned bo = __ballot_sync(0xffffffffu, r0 > r1);
        if (lane == 0) {
            sd[(y - 1) * 16 + warp * 2]     = be;
            sd[(y - 1) * 16 + warp * 2 + 1] = bo;
        }
        float nr1 = cc.y + fmaxf(r1, r0);
        r0 = cc.x + fmaxf(r0, vd0);
        r1 = nr1;
        if (lane == 31) bnd[(y & 1) * 8 + warp] = r1;
        __syncthreads();
        bl = (warp > 0) ? bnd[(y & 1) * 8 + warp - 1] : NEGF;
    }
    // y = 4..TY-1
    for (int g = 4; g < TY; g += 4) {
#pragma unroll
        for (int j = 0; j < 4; ++j) {
            int y = g + j;
            float2 cc = pf[j];
            if (y + 4 < TY) pf[j] = lp2[(size_t)(y + 4) * 256 + tid];
            float vd0 = __shfl_up_sync(0xffffffffu, r1, 1);
            if (lane == 0) vd0 = bl;
            unsigned be = __ballot_sync(0xffffffffu, vd0 > r0);
            unsigned bo = __ballot_sync(0xffffffffu, r0 > r1);
            if (lane == 0) {
                sd[(y - 1) * 16 + warp * 2]     = be;
                sd[(y - 1) * 16 + warp * 2 + 1] = bo;
            }
            float nr1 = cc.y + fmaxf(r1, r0);
            r0 = cc.x + fmaxf(r0, vd0);
            r1 = nr1;
            if (lane == 31) bnd[(y & 1) * 8 + warp] = r1;
            __syncthreads();
            bl = (warp > 0) ? bnd[(y & 1) * 8 + warp - 1] : NEGF;
        }
    }

    int txL = xlen[b], tyL = ylen[b];
    if (tid == 0) {
        int idx = txL - 1;
        for (int y = TY - 1; y >= 0; --y) {
            if (y >= tyL) { g_xs[b * TY + y] = -1; continue; }
            sxs[y] = idx;
            g_xs[b * TY + y] = idx;
            int mv = 0;
            if (idx > 0) {
                if (idx == y) {
                    mv = 1;
                } else {
                    unsigned w = sd[(y - 1) * 16 + ((idx >> 6) << 1) + (idx & 1)];
                    mv = (w >> ((idx >> 1) & 31)) & 1;
                }
            }
            idx -= mv;
        }
    }
    __syncthreads();
#pragma unroll
    for (int h = 0; h < 2; ++h) {
        int x = tid + h * 256;
        float dv = 0.0f;
        if (x < txL) {
            int lo = 0, hi = tyL;
            while (lo < hi) { int mid = (lo + hi) >> 1; if (sxs[mid] < x) lo = mid + 1; else hi = mid; }
            int start = lo;
            hi = tyL;
            while (lo < hi) { int mid = (lo + hi) >> 1; if (sxs[mid] < x + 1) lo = mid + 1; else hi = mid; }
            dv = log1pf((float)(lo - start));
        }
        out[OFF_DUR + b * TX + x] = dv;
    }
}

// ---------------- kernel 5: gathers + attn ones ----------------
__global__ void __launch_bounds__(256) gather_kernel(float* __restrict__ out) {
    int t = blockIdx.x * 256 + threadIdx.x;
    if (t >= BB * TY * 20) return;
    int bs = t / 20;
    int c4 = (t % 20) * 4;
    int b  = bs >> 11;
    int xs = g_xs[bs];
    float4 m = make_float4(0.f, 0.f, 0.f, 0.f), l = m;
    if (xs >= 0) {
        size_t rb = ((size_t)b * TX + xs) * CC + c4;
        m = *(const float4*)&g_omT[rb];
        l = *(const float4*)&g_olsT[rb];
        if (c4 == 0) out[OFF_AT + (size_t)bs * TX + xs] = 1.0f;
    }
    *(float4*)&out[OFF_M + (size_t)bs * CC + c4] = m;
    *(float4*)&out[OFF_L + (size_t)bs * CC + c4] = l;
}

// ---------------- launch ----------------
extern "C" void kernel_launch(void* const* d_in, const int* in_sizes, int n_in,
                              void* d_out, int out_size) {
    const float* om   = (const float*)d_in[0];
    const float* ols  = (const float*)d_in[1];
    const float* z    = (const float*)d_in[2];
    const int*   xlen = (const int*)d_in[3];
    const int*   ylen = (const int*)d_in[4];
    float* out = (float*)d_out;

    static bool attr_set = false;
    if (!attr_set) {
        cudaFuncSetAttribute(fwd_kernel, cudaFuncAttributeMaxDynamicSharedMemorySize, FWD_SMEM);
        cudaFuncSetAttribute(gemm_logp, cudaFuncAttributeMaxDynamicSharedMemorySize, GEMM_SMEM);
        attr_set = true;
    }

    prep_kernel<<<dim3(TX / 128, BB), 128>>>(om, ols);
    pre_out<<<496, 512>>>(z, om, ols, ylen, out);
    gemm_logp<<<dim3(TX / 128, TY / 128, BB), 256, GEMM_SMEM>>>(z, xlen, ylen);
    fwd_kernel<<<BB, 256, FWD_SMEM>>>(xlen, ylen, out);
    gather_kernel<<<(BB * TY * 20 + 255) / 256, 256>>>(out);
}